// round 14
// baseline (speedup 1.0000x reference)
#include <cuda_runtime.h>
#include <cuda_fp16.h>
#include <cstdint>

#define DIN     4096
#define RANK    64
#define MTOT    8192
#define NR      512
#define HCOLS   1536
#define DOUT    4096
#define OUTCOLS 12288

__device__ __align__(16) __half g_Xh[(size_t)MTOT * DIN];    // 64 MB
__device__ __align__(16) __half g_Ah[(size_t)HCOLS * DIN];   // 12.5 MB  [j][k]
__device__ __align__(16) __half g_Bh[(size_t)3 * DOUT * NR]; // 12.5 MB  [comp][n][k]
__device__ __align__(16) __half g_Hh[(size_t)MTOT * HCOLS];  // 25 MB    [m][j]
__device__ int g_rowcnt[MTOT / 128];                         // H row-block ready (0..12)
__device__ int g_ctr[2];                                     // dynamic tile counters

// ---------------------------------------------------------------------------
// PTX helpers
// ---------------------------------------------------------------------------
__device__ __forceinline__ uint32_t s2u(const void* p) {
    uint32_t a;
    asm("{ .reg .u64 t; cvta.to.shared.u64 t, %1; cvt.u32.u64 %0, t; }" : "=r"(a) : "l"(p));
    return a;
}
__device__ __forceinline__ void cpasync16(uint32_t dst, const void* src) {
    asm volatile("cp.async.cg.shared.global [%0], [%1], 16;" :: "r"(dst), "l"(src) : "memory");
}
#define CP_COMMIT()  asm volatile("cp.async.commit_group;" ::: "memory")
#define CP_WAIT(n)   asm volatile("cp.async.wait_group %0;" :: "n"(n) : "memory")

__device__ __forceinline__ void ldsm4(uint32_t* r, uint32_t a) {
    asm volatile("ldmatrix.sync.aligned.m8n8.x4.shared.b16 {%0,%1,%2,%3}, [%4];"
                 : "=r"(r[0]), "=r"(r[1]), "=r"(r[2]), "=r"(r[3]) : "r"(a));
}
__device__ __forceinline__ void mma16816(float* c, const uint32_t* a, const uint32_t* b) {
    asm volatile(
        "mma.sync.aligned.m16n8k16.row.col.f32.f16.f16.f32 "
        "{%0,%1,%2,%3},{%4,%5,%6,%7},{%8,%9},{%0,%1,%2,%3};"
        : "+f"(c[0]), "+f"(c[1]), "+f"(c[2]), "+f"(c[3])
        : "r"(a[0]), "r"(a[1]), "r"(a[2]), "r"(a[3]), "r"(b[0]), "r"(b[1]));
}
__device__ __forceinline__ uint32_t swz(int row, int chunk) {
    return (uint32_t)(row * 8 + (chunk ^ (row & 7))) * 16u;
}

// ---------------------------------------------------------------------------
// Merged prep wave (R12/R13, validated) + flag/counter init folded into job 0.
// Kernel boundary before fused_k orders everything; graph replay re-inits.
// ---------------------------------------------------------------------------
__global__ void __launch_bounds__(256)
prep_k(const float* __restrict__ x,
       const float* __restrict__ qA, const float* __restrict__ kA,
       const float* __restrict__ vA,
       const float* __restrict__ qB, const float* __restrict__ kB,
       const float* __restrict__ vB) {
    __shared__ float t[32][33];
    const int job = blockIdx.x;
    const int tid = threadIdx.x;

    if (job == 0) {   // fold init_flags here (saves a kernel launch)
        if (tid < MTOT / 128) g_rowcnt[tid] = 0;
        if (tid >= 64 && tid < 66) g_ctr[tid - 64] = 0;
    }

    if (job < 2048) {   // convx: 16384 contiguous floats per job
        const size_t base = (size_t)job * 16384;
        const float* src = x + base;
        __half* dst = g_Xh + base;
        #pragma unroll
        for (int it = 0; it < 8; it++) {
            const size_t i = (size_t)tid * 8 + (size_t)it * 2048;
            float4 a = *(const float4*)(src + i);
            float4 b = *(const float4*)(src + i + 4);
            __half2 h[4];
            h[0] = __floats2half2_rn(a.x, a.y);
            h[1] = __floats2half2_rn(a.z, a.w);
            h[2] = __floats2half2_rn(b.x, b.y);
            h[3] = __floats2half2_rn(b.z, b.w);
            *(uint4*)(dst + i) = *(uint4*)h;
        }
        return;
    }

    const int tx = tid & 31, ty = tid >> 5;   // 32 x 8

    if (job < 2048 + 6144) {   // transA
        const int z = job - 2048;
        const int bz = z >> 8, rem = z & 255;
        const int by = rem >> 7, bx = rem & 127;
        const int comp = bz >> 3, n = bz & 7;
        const float* src = (comp == 0 ? qA : (comp == 1 ? kA : vA)) + (size_t)n * DIN * RANK;
        const int i0 = bx * 32, r0 = by * 32;
        #pragma unroll
        for (int q = 0; q < 4; q++)
            t[ty + q * 8][tx] = src[(size_t)(i0 + ty + q * 8) * RANK + r0 + tx];
        __syncthreads();
        const size_t jb = (size_t)(comp * 512 + n * 64 + r0);
        #pragma unroll
        for (int q = 0; q < 4; q++)
            g_Ah[(jb + ty + q * 8) * DIN + i0 + tx] = __float2half_rn(t[tx][ty + q * 8]);
        return;
    }

    {   // transB
        const int z = job - 2048 - 6144;
        const int bz = z >> 11, rem = z & 2047;
        const int by = rem >> 4, bx = rem & 15;
        const float* src = (bz == 0 ? qB : (bz == 1 ? kB : vB));
        const int k0 = bx * 32, n0 = by * 32;
        #pragma unroll
        for (int q = 0; q < 4; q++)
            t[ty + q * 8][tx] = src[(size_t)(k0 + ty + q * 8) * DOUT + n0 + tx];
        __syncthreads();
        __half* dst = g_Bh + (size_t)bz * DOUT * NR;
        #pragma unroll
        for (int q = 0; q < 4; q++)
            dst[(size_t)(n0 + ty + q * 8) * NR + k0 + tx] =
                __float2half_rn(t[tx][ty + q * 8]);
    }
}

// ---------------------------------------------------------------------------
// Dynamic streaming GEMM (R13 champion): tiles claimed from a global atomic
// counter with one-tile lookahead (claim at kt==0, read at kt==1) so the
// cp.async stream never drains across tiles. Exactly one commit_group per
// iteration (empty at stream end) keeps CP_WAIT(1) accounting uniform.
// Tile 128x128, warp m64xn64, BK=64, 3 stages, 128 thr, 2 CTAs/SM.
// ---------------------------------------------------------------------------
constexpr int STAGE_B = 32 * 1024;
constexpr int BSTAGES = 3;

struct TP2 { const __half* Ag; const __half* Bg; };

template <int NT, int LDA, int LDB, class TF, class GF, class EF>
__device__ __forceinline__ void dyn_stream(int* ctr, int ntile, TF tilef, GF guardf,
                                           EF epif, char* sm, int* cslot) {
    const int tid  = threadIdx.x;
    const int lane = tid & 31;
    const int wid  = tid >> 5;
    const int wm   = wid & 1;
    const int wn   = wid >> 1;
    uint32_t smu = s2u(sm);

    auto issue = [&](TP2 tp, int kt, int slot) {
        const uint32_t sa = smu + slot * STAGE_B;
        const uint32_t sb = sa + 16384;
        const char* agb = (const char*)tp.Ag + (size_t)kt * 128;
        const char* bgb = (const char*)tp.Bg + (size_t)kt * 128;
        #pragma unroll
        for (int i = 0; i < 8; i++) {
            int lin = tid + 128 * i;
            int row = lin >> 3, c = lin & 7;
            cpasync16(sa + swz(row, c), agb + (size_t)row * LDA * 2 + c * 16);
        }
        #pragma unroll
        for (int i = 0; i < 8; i++) {
            int lin = tid + 128 * i;
            int row = lin >> 3, c = lin & 7;
            cpasync16(sb + swz(row, c), bgb + (size_t)row * LDB * 2 + c * 16);
        }
        CP_COMMIT();
    };

    // claim first tile
    if (tid == 0) *cslot = atomicAdd(ctr, 1);
    __syncthreads();
    int cur = *cslot;
    if (cur >= ntile) return;

    guardf(cur);
    TP2 tpc = tilef(cur);
    issue(tpc, 0, 0);
    issue(tpc, 1, 1);

    float acc[4][8][4];
    uint32_t afb[2][4][4], bfb[2][4][4];
    int nxt = ntile;
    TP2 tpn = tpc;
    bool have_nxt = false;
    int s = 0;
    bool done = false;

    #pragma unroll 1
    while (!done) {
        #pragma unroll 1
        for (int kt = 0; kt < NT; kt++, s++) {
            CP_WAIT(1);
            __syncthreads();

            if (kt == 0) {
                if (tid == 0) *cslot = atomicAdd(ctr, 1);   // claim successor
                #pragma unroll
                for (int i = 0; i < 4; i++)
                    #pragma unroll
                    for (int j = 0; j < 8; j++)
                        #pragma unroll
                        for (int q = 0; q < 4; q++) acc[i][j][q] = 0.f;
            }
            if (kt == 1) {                                   // barrier-ordered read
                nxt = *cslot;
                have_nxt = (nxt < ntile);
                if (have_nxt) tpn = tilef(nxt);
            }

            {   // issue ktile s+2 (cur, nxt, or empty)
                const int slot2 = (s + 2) % BSTAGES;
                const int k2 = kt + 2;
                if (k2 < NT) {
                    issue(tpc, k2, slot2);
                } else if (have_nxt) {
                    if (k2 == NT) guardf(nxt);
                    issue(tpn, k2 - NT, slot2);
                } else {
                    CP_COMMIT();                             // empty group keeps accounting
                }
            }

            const uint32_t sa = smu + (s % BSTAGES) * STAGE_B;
            const uint32_t sb = sa + 16384;

            // preload ks=0 fragments
            #pragma unroll
            for (int mt = 0; mt < 4; mt++)
                ldsm4(afb[0][mt], sa + swz(wm * 64 + mt * 16 + (lane & 15), (lane >> 4)));
            #pragma unroll
            for (int ng = 0; ng < 4; ng++)
                ldsm4(bfb[0][ng], sb + swz(wn * 64 + ng * 16 + (lane & 7) + ((lane >> 4) << 3),
                                           ((lane >> 3) & 1)));

            #pragma unroll
            for (int ks = 0; ks < 4; ks++) {
                const int curb = ks & 1, nxtb = curb ^ 1;
                if (ks < 3) {
                    #pragma unroll
                    for (int mt = 0; mt < 4; mt++)
                        ldsm4(afb[nxtb][mt],
                              sa + swz(wm * 64 + mt * 16 + (lane & 15),
                                       (ks + 1) * 2 + (lane >> 4)));
                    #pragma unroll
                    for (int ng = 0; ng < 4; ng++)
                        ldsm4(bfb[nxtb][ng],
                              sb + swz(wn * 64 + ng * 16 + (lane & 7) + ((lane >> 4) << 3),
                                       (ks + 1) * 2 + ((lane >> 3) & 1)));
                }
                #pragma unroll
                for (int mt = 0; mt < 4; mt++)
                    #pragma unroll
                    for (int ng = 0; ng < 4; ng++) {
                        mma16816(acc[mt][ng * 2 + 0], afb[curb][mt], &bfb[curb][ng][0]);
                        mma16816(acc[mt][ng * 2 + 1], afb[curb][mt], &bfb[curb][ng][2]);
                    }
            }

            if (kt == NT - 1) epif(cur, acc);
        }
        if (have_nxt) { cur = nxt; tpc = tpn; have_nxt = false; }
        else done = true;
    }
    CP_WAIT(0);
    __syncthreads();
}

// ---------------------------------------------------------------------------
// Fused persistent kernel: phase1 gemm1 (dynamic, flags), phase2 gemm2
// (dynamic, flag-gated). Grid = 2 * num_SMs => full residency, spin-safe.
// ---------------------------------------------------------------------------
__global__ void __launch_bounds__(128, 2)
fused_k(const float* __restrict__ masks, const float* __restrict__ scaling,
        float* __restrict__ out) {
    extern __shared__ __align__(16) char sm[];
    int* cslot = (int*)(sm + BSTAGES * STAGE_B);
    const int tid  = threadIdx.x;
    const int lane = tid & 31;
    const int wid  = tid >> 5;
    const int wm   = wid & 1;
    const int wn   = wid >> 1;

    // ---------------- Phase 1: gemm1 (768 tiles, NT=64) ----------------
    {
        auto tilef = [&](int tile) -> TP2 {
            int row0 = (tile / 12) << 7, col0 = (tile % 12) << 7;
            return { g_Xh + (size_t)row0 * DIN, g_Ah + (size_t)col0 * DIN };
        };
        auto guardf = [&](int) {};
        auto epif = [&](int tile, float (&acc)[4][8][4]) {
            int rb = tile / 12;
            int row0 = rb << 7, col0 = (tile % 12) << 7;
            const int nad = ((col0 + wn * 64) >> 6) & 7;
            const int b   = row0 >> 11;
            const float coef = scaling[nad] * masks[nad * 4 + b];
            #pragma unroll
            for (int mt = 0; mt < 4; mt++) {
                #pragma unroll
                for (int ni = 0; ni < 8; ni++) {
                    int r = row0 + wm * 64 + mt * 16 + (lane >> 2);
                    int c = col0 + wn * 64 + ni * 8 + 2 * (lane & 3);
                    *(__half2*)(g_Hh + (size_t)r * HCOLS + c) =
                        __floats2half2_rn(acc[mt][ni][0] * coef, acc[mt][ni][1] * coef);
                    *(__half2*)(g_Hh + (size_t)(r + 8) * HCOLS + c) =
                        __floats2half2_rn(acc[mt][ni][2] * coef, acc[mt][ni][3] * coef);
                }
            }
            __threadfence();
            __syncthreads();
            if (tid == 0) atomicAdd(&g_rowcnt[rb], 1);
        };
        dyn_stream<64, DIN, DIN>(&g_ctr[0], 768, tilef, guardf, epif, sm, cslot);
    }

    // ---------------- Phase 2: gemm2 (6144 tiles, NT=8) ----------------
    {
        auto tilef = [&](int tile) -> TP2 {
            int row0 = (tile / 96) << 7, col0 = (tile % 96) << 7;
            int comp = col0 >> 12, cl = col0 & 4095;
            return { g_Hh + (size_t)row0 * HCOLS + comp * NR,
                     g_Bh + (size_t)comp * DOUT * NR + (size_t)cl * NR };
        };
        auto guardf = [&](int tile) {
            int rb = tile / 96;
            if (tid == 0) {
                int v;
                do {
                    asm volatile("ld.global.acquire.gpu.b32 %0, [%1];"
                                 : "=r"(v) : "l"(g_rowcnt + rb) : "memory");
                } while (v < 12);
            }
            __syncthreads();
        };
        auto epif = [&](int tile, float (&acc)[4][8][4]) {
            int row0 = (tile / 96) << 7, col0 = (tile % 96) << 7;
            #pragma unroll
            for (int mt = 0; mt < 4; mt++) {
                #pragma unroll
                for (int ni = 0; ni < 8; ni++) {
                    int r = row0 + wm * 64 + mt * 16 + (lane >> 2);
                    int c = col0 + wn * 64 + ni * 8 + 2 * (lane & 3);
                    *(float2*)(out + (size_t)r * OUTCOLS + c) =
                        make_float2(acc[mt][ni][0], acc[mt][ni][1]);
                    *(float2*)(out + (size_t)(r + 8) * OUTCOLS + c) =
                        make_float2(acc[mt][ni][2], acc[mt][ni][3]);
                }
            }
        };
        dyn_stream<8, HCOLS, NR>(&g_ctr[1], 6144, tilef, guardf, epif, sm, cslot);
    }
}

// ---------------------------------------------------------------------------
extern "C" void kernel_launch(void* const* d_in, const int* in_sizes, int n_in,
                              void* d_out, int out_size) {
    const float* x       = (const float*)d_in[0];
    const float* masks   = (const float*)d_in[2];
    const float* scaling = (const float*)d_in[3];
    const float* qA      = (const float*)d_in[4];
    const float* qB      = (const float*)d_in[5];
    const float* kA      = (const float*)d_in[6];
    const float* kB      = (const float*)d_in[7];
    const float* vA      = (const float*)d_in[8];
    const float* vB      = (const float*)d_in[9];
    float* out = (float*)d_out;

    static int nsm = 0;
    if (nsm == 0) {
        cudaDeviceGetAttribute(&nsm, cudaDevAttrMultiProcessorCount, 0);
        if (nsm <= 0) nsm = 148;
    }

    const int SMEM = BSTAGES * STAGE_B + 16;   // stages + claim slot
    cudaFuncSetAttribute(fused_k, cudaFuncAttributeMaxDynamicSharedMemorySize, SMEM);

    prep_k<<<2048 + 6144 + 6144, 256>>>(x, qA, kA, vA, qB, kB, vB);
    fused_k<<<2 * nsm, 128, SMEM>>>(masks, scaling, out);
}

// round 15
// speedup vs baseline: 1.0128x; 1.0128x over previous
#include <cuda_runtime.h>
#include <cuda_fp16.h>
#include <cstdint>

#define DIN     4096
#define RANK    64
#define MTOT    8192
#define NR      512
#define HCOLS   1536
#define DOUT    4096
#define OUTCOLS 12288

__device__ __align__(16) __half g_Xh[(size_t)MTOT * DIN];    // 64 MB
__device__ __align__(16) __half g_Ah[(size_t)HCOLS * DIN];   // 12.5 MB  [j][k]
__device__ __align__(16) __half g_Bh[(size_t)3 * DOUT * NR]; // 12.5 MB  [comp][n][k]
__device__ __align__(16) __half g_Hh[(size_t)MTOT * HCOLS];  // 25 MB    [m][j]
__device__ int g_rowcnt[MTOT / 128];                         // H row-block ready (0..12)
__device__ int g_ctr[2];                                     // dynamic tile counters

// ---------------------------------------------------------------------------
// PTX helpers
// ---------------------------------------------------------------------------
__device__ __forceinline__ uint32_t s2u(const void* p) {
    uint32_t a;
    asm("{ .reg .u64 t; cvta.to.shared.u64 t, %1; cvt.u32.u64 %0, t; }" : "=r"(a) : "l"(p));
    return a;
}
__device__ __forceinline__ void cpasync16(uint32_t dst, const void* src) {
    asm volatile("cp.async.cg.shared.global [%0], [%1], 16;" :: "r"(dst), "l"(src) : "memory");
}
#define CP_COMMIT()  asm volatile("cp.async.commit_group;" ::: "memory")
#define CP_WAIT(n)   asm volatile("cp.async.wait_group %0;" :: "n"(n) : "memory")

__device__ __forceinline__ void ldsm4(uint32_t* r, uint32_t a) {
    asm volatile("ldmatrix.sync.aligned.m8n8.x4.shared.b16 {%0,%1,%2,%3}, [%4];"
                 : "=r"(r[0]), "=r"(r[1]), "=r"(r[2]), "=r"(r[3]) : "r"(a));
}
__device__ __forceinline__ void mma16816(float* c, const uint32_t* a, const uint32_t* b) {
    asm volatile(
        "mma.sync.aligned.m16n8k16.row.col.f32.f16.f16.f32 "
        "{%0,%1,%2,%3},{%4,%5,%6,%7},{%8,%9},{%0,%1,%2,%3};"
        : "+f"(c[0]), "+f"(c[1]), "+f"(c[2]), "+f"(c[3])
        : "r"(a[0]), "r"(a[1]), "r"(a[2]), "r"(a[3]), "r"(b[0]), "r"(b[1]));
}
__device__ __forceinline__ uint32_t swz(int row, int chunk) {
    return (uint32_t)(row * 8 + (chunk ^ (row & 7))) * 16u;
}

// ---------------------------------------------------------------------------
// Merged prep wave (validated; runs at the ~6.3TB/s LTS cap) + init in job 0.
// ---------------------------------------------------------------------------
__global__ void __launch_bounds__(256)
prep_k(const float* __restrict__ x,
       const float* __restrict__ qA, const float* __restrict__ kA,
       const float* __restrict__ vA,
       const float* __restrict__ qB, const float* __restrict__ kB,
       const float* __restrict__ vB) {
    __shared__ float t[32][33];
    const int job = blockIdx.x;
    const int tid = threadIdx.x;

    if (job == 0) {   // flag/counter init (kernel boundary orders it)
        if (tid < MTOT / 128) g_rowcnt[tid] = 0;
        if (tid >= 64 && tid < 66) g_ctr[tid - 64] = 0;
    }

    if (job < 2048) {   // convx: 16384 contiguous floats per job
        const size_t base = (size_t)job * 16384;
        const float* src = x + base;
        __half* dst = g_Xh + base;
        #pragma unroll
        for (int it = 0; it < 8; it++) {
            const size_t i = (size_t)tid * 8 + (size_t)it * 2048;
            float4 a = *(const float4*)(src + i);
            float4 b = *(const float4*)(src + i + 4);
            __half2 h[4];
            h[0] = __floats2half2_rn(a.x, a.y);
            h[1] = __floats2half2_rn(a.z, a.w);
            h[2] = __floats2half2_rn(b.x, b.y);
            h[3] = __floats2half2_rn(b.z, b.w);
            *(uint4*)(dst + i) = *(uint4*)h;
        }
        return;
    }

    const int tx = tid & 31, ty = tid >> 5;   // 32 x 8

    if (job < 2048 + 6144) {   // transA
        const int z = job - 2048;
        const int bz = z >> 8, rem = z & 255;
        const int by = rem >> 7, bx = rem & 127;
        const int comp = bz >> 3, n = bz & 7;
        const float* src = (comp == 0 ? qA : (comp == 1 ? kA : vA)) + (size_t)n * DIN * RANK;
        const int i0 = bx * 32, r0 = by * 32;
        #pragma unroll
        for (int q = 0; q < 4; q++)
            t[ty + q * 8][tx] = src[(size_t)(i0 + ty + q * 8) * RANK + r0 + tx];
        __syncthreads();
        const size_t jb = (size_t)(comp * 512 + n * 64 + r0);
        #pragma unroll
        for (int q = 0; q < 4; q++)
            g_Ah[(jb + ty + q * 8) * DIN + i0 + tx] = __float2half_rn(t[tx][ty + q * 8]);
        return;
    }

    {   // transB
        const int z = job - 2048 - 6144;
        const int bz = z >> 11, rem = z & 2047;
        const int by = rem >> 4, bx = rem & 15;
        const float* src = (bz == 0 ? qB : (bz == 1 ? kB : vB));
        const int k0 = bx * 32, n0 = by * 32;
        #pragma unroll
        for (int q = 0; q < 4; q++)
            t[ty + q * 8][tx] = src[(size_t)(k0 + ty + q * 8) * DOUT + n0 + tx];
        __syncthreads();
        __half* dst = g_Bh + (size_t)bz * DOUT * NR;
        #pragma unroll
        for (int q = 0; q < 4; q++)
            dst[(size_t)(n0 + ty + q * 8) * NR + k0 + tx] =
                __float2half_rn(t[tx][ty + q * 8]);
    }
}

// ---------------------------------------------------------------------------
// Dynamic streaming GEMM (champion core). Guard for the NEXT tile now runs at
// claim-read time (kt==1), giving the producer flag NT-3 ktiles of slack
// before its first cp.async would consume it.
// ---------------------------------------------------------------------------
constexpr int STAGE_B = 32 * 1024;
constexpr int BSTAGES = 3;

struct TP2 { const __half* Ag; const __half* Bg; };

template <int NT, int LDA, int LDB, class TF, class GF, class EF>
__device__ __forceinline__ void dyn_stream(int* ctr, int ntile, TF tilef, GF guardf,
                                           EF epif, char* sm, int* cslot) {
    const int tid  = threadIdx.x;
    const int lane = tid & 31;
    const int wid  = tid >> 5;
    const int wm   = wid & 1;
    const int wn   = wid >> 1;
    uint32_t smu = s2u(sm);

    auto issue = [&](TP2 tp, int kt, int slot) {
        const uint32_t sa = smu + slot * STAGE_B;
        const uint32_t sb = sa + 16384;
        const char* agb = (const char*)tp.Ag + (size_t)kt * 128;
        const char* bgb = (const char*)tp.Bg + (size_t)kt * 128;
        #pragma unroll
        for (int i = 0; i < 8; i++) {
            int lin = tid + 128 * i;
            int row = lin >> 3, c = lin & 7;
            cpasync16(sa + swz(row, c), agb + (size_t)row * LDA * 2 + c * 16);
        }
        #pragma unroll
        for (int i = 0; i < 8; i++) {
            int lin = tid + 128 * i;
            int row = lin >> 3, c = lin & 7;
            cpasync16(sb + swz(row, c), bgb + (size_t)row * LDB * 2 + c * 16);
        }
        CP_COMMIT();
    };

    // claim first tile
    if (tid == 0) *cslot = atomicAdd(ctr, 1);
    __syncthreads();
    int cur = *cslot;
    if (cur >= ntile) return;

    guardf(cur);
    TP2 tpc = tilef(cur);
    issue(tpc, 0, 0);
    issue(tpc, 1, 1);

    float acc[4][8][4];
    uint32_t afb[2][4][4], bfb[2][4][4];
    int nxt = ntile;
    TP2 tpn = tpc;
    bool have_nxt = false;
    int s = 0;
    bool done = false;

    #pragma unroll 1
    while (!done) {
        #pragma unroll 1
        for (int kt = 0; kt < NT; kt++, s++) {
            CP_WAIT(1);
            __syncthreads();

            if (kt == 0) {
                if (tid == 0) *cslot = atomicAdd(ctr, 1);   // claim successor
                #pragma unroll
                for (int i = 0; i < 4; i++)
                    #pragma unroll
                    for (int j = 0; j < 8; j++)
                        #pragma unroll
                        for (int q = 0; q < 4; q++) acc[i][j][q] = 0.f;
            }
            if (kt == 1) {                                   // barrier-ordered read
                nxt = *cslot;
                have_nxt = (nxt < ntile);
                if (have_nxt) {
                    tpn = tilef(nxt);
                    guardf(nxt);    // hoisted: NT-3 ktiles of slack before first use
                }
            }

            {   // issue ktile s+2 (cur, nxt, or empty)
                const int slot2 = (s + 2) % BSTAGES;
                const int k2 = kt + 2;
                if (k2 < NT) {
                    issue(tpc, k2, slot2);
                } else if (have_nxt) {
                    issue(tpn, k2 - NT, slot2);
                } else {
                    CP_COMMIT();                             // empty group keeps accounting
                }
            }

            const uint32_t sa = smu + (s % BSTAGES) * STAGE_B;
            const uint32_t sb = sa + 16384;

            // preload ks=0 fragments
            #pragma unroll
            for (int mt = 0; mt < 4; mt++)
                ldsm4(afb[0][mt], sa + swz(wm * 64 + mt * 16 + (lane & 15), (lane >> 4)));
            #pragma unroll
            for (int ng = 0; ng < 4; ng++)
                ldsm4(bfb[0][ng], sb + swz(wn * 64 + ng * 16 + (lane & 7) + ((lane >> 4) << 3),
                                           ((lane >> 3) & 1)));

            #pragma unroll
            for (int ks = 0; ks < 4; ks++) {
                const int curb = ks & 1, nxtb = curb ^ 1;
                if (ks < 3) {
                    #pragma unroll
                    for (int mt = 0; mt < 4; mt++)
                        ldsm4(afb[nxtb][mt],
                              sa + swz(wm * 64 + mt * 16 + (lane & 15),
                                       (ks + 1) * 2 + (lane >> 4)));
                    #pragma unroll
                    for (int ng = 0; ng < 4; ng++)
                        ldsm4(bfb[nxtb][ng],
                              sb + swz(wn * 64 + ng * 16 + (lane & 7) + ((lane >> 4) << 3),
                                       (ks + 1) * 2 + ((lane >> 3) & 1)));
                }
                #pragma unroll
                for (int mt = 0; mt < 4; mt++)
                    #pragma unroll
                    for (int ng = 0; ng < 4; ng++) {
                        mma16816(acc[mt][ng * 2 + 0], afb[curb][mt], &bfb[curb][ng][0]);
                        mma16816(acc[mt][ng * 2 + 1], afb[curb][mt], &bfb[curb][ng][2]);
                    }
            }

            if (kt == NT - 1) epif(cur, acc);
        }
        if (have_nxt) { cur = nxt; tpc = tpn; have_nxt = false; }
        else done = true;
    }
    CP_WAIT(0);
    __syncthreads();
}

// ---------------------------------------------------------------------------
// Fused persistent kernel: phase1 gemm1 (dynamic, flags), phase2 gemm2
// (dynamic, flag-gated). Grid = 2 * num_SMs => full residency, spin-safe.
// ---------------------------------------------------------------------------
__global__ void __launch_bounds__(128, 2)
fused_k(const float* __restrict__ masks, const float* __restrict__ scaling,
        float* __restrict__ out) {
    extern __shared__ __align__(16) char sm[];
    int* cslot = (int*)(sm + BSTAGES * STAGE_B);
    const int tid  = threadIdx.x;
    const int lane = tid & 31;
    const int wid  = tid >> 5;
    const int wm   = wid & 1;
    const int wn   = wid >> 1;

    // ---------------- Phase 1: gemm1 (768 tiles, NT=64) ----------------
    {
        auto tilef = [&](int tile) -> TP2 {
            int row0 = (tile / 12) << 7, col0 = (tile % 12) << 7;
            return { g_Xh + (size_t)row0 * DIN, g_Ah + (size_t)col0 * DIN };
        };
        auto guardf = [&](int) {};
        auto epif = [&](int tile, float (&acc)[4][8][4]) {
            int rb = tile / 12;
            int row0 = rb << 7, col0 = (tile % 12) << 7;
            const int nad = ((col0 + wn * 64) >> 6) & 7;
            const int b   = row0 >> 11;
            const float coef = scaling[nad] * masks[nad * 4 + b];
            #pragma unroll
            for (int mt = 0; mt < 4; mt++) {
                #pragma unroll
                for (int ni = 0; ni < 8; ni++) {
                    int r = row0 + wm * 64 + mt * 16 + (lane >> 2);
                    int c = col0 + wn * 64 + ni * 8 + 2 * (lane & 3);
                    *(__half2*)(g_Hh + (size_t)r * HCOLS + c) =
                        __floats2half2_rn(acc[mt][ni][0] * coef, acc[mt][ni][1] * coef);
                    *(__half2*)(g_Hh + (size_t)(r + 8) * HCOLS + c) =
                        __floats2half2_rn(acc[mt][ni][2] * coef, acc[mt][ni][3] * coef);
                }
            }
            __threadfence();
            __syncthreads();
            if (tid == 0) atomicAdd(&g_rowcnt[rb], 1);
        };
        dyn_stream<64, DIN, DIN>(&g_ctr[0], 768, tilef, guardf, epif, sm, cslot);
    }

    // ---------------- Phase 2: gemm2 (6144 tiles, NT=8) ----------------
    {
        auto tilef = [&](int tile) -> TP2 {
            int row0 = (tile / 96) << 7, col0 = (tile % 96) << 7;
            int comp = col0 >> 12, cl = col0 & 4095;
            return { g_Hh + (size_t)row0 * HCOLS + comp * NR,
                     g_Bh + (size_t)comp * DOUT * NR + (size_t)cl * NR };
        };
        auto guardf = [&](int tile) {
            int rb = tile / 96;
            if (tid == 0) {
                int v;
                do {
                    asm volatile("ld.global.acquire.gpu.b32 %0, [%1];"
                                 : "=r"(v) : "l"(g_rowcnt + rb) : "memory");
                } while (v < 12);
            }
            __syncthreads();
        };
        auto epif = [&](int tile, float (&acc)[4][8][4]) {
            int row0 = (tile / 96) << 7, col0 = (tile % 96) << 7;
            #pragma unroll
            for (int mt = 0; mt < 4; mt++) {
                #pragma unroll
                for (int ni = 0; ni < 8; ni++) {
                    int r = row0 + wm * 64 + mt * 16 + (lane >> 2);
                    int c = col0 + wn * 64 + ni * 8 + 2 * (lane & 3);
                    *(float2*)(out + (size_t)r * OUTCOLS + c) =
                        make_float2(acc[mt][ni][0], acc[mt][ni][1]);
                    *(float2*)(out + (size_t)(r + 8) * OUTCOLS + c) =
                        make_float2(acc[mt][ni][2], acc[mt][ni][3]);
                }
            }
        };
        dyn_stream<8, HCOLS, NR>(&g_ctr[1], 6144, tilef, guardf, epif, sm, cslot);
    }
}

// ---------------------------------------------------------------------------
extern "C" void kernel_launch(void* const* d_in, const int* in_sizes, int n_in,
                              void* d_out, int out_size) {
    const float* x       = (const float*)d_in[0];
    const float* masks   = (const float*)d_in[2];
    const float* scaling = (const float*)d_in[3];
    const float* qA      = (const float*)d_in[4];
    const float* qB      = (const float*)d_in[5];
    const float* kA      = (const float*)d_in[6];
    const float* kB      = (const float*)d_in[7];
    const float* vA      = (const float*)d_in[8];
    const float* vB      = (const float*)d_in[9];
    float* out = (float*)d_out;

    static int nsm = 0;
    if (nsm == 0) {
        cudaDeviceGetAttribute(&nsm, cudaDevAttrMultiProcessorCount, 0);
        if (nsm <= 0) nsm = 148;
    }

    const int SMEM = BSTAGES * STAGE_B + 16;   // stages + claim slot
    cudaFuncSetAttribute(fused_k, cudaFuncAttributeMaxDynamicSharedMemorySize, SMEM);

    prep_k<<<2048 + 6144 + 6144, 256>>>(x, qA, kA, vA, qB, kB, vB);
    fused_k<<<2 * nsm, 128, SMEM>>>(masks, scaling, out);
}